// round 14
// baseline (speedup 1.0000x reference)
#include <cuda_runtime.h>
#include <cuda_fp16.h>
#include <math.h>
#include <stdint.h>

// Problem constants
#define BATCH 32
#define SEQ   512
#define CDIM  512
#define NHEAD 8
#define DHEAD 64
#define MROWS (BATCH * SEQ)        // 16384
#define FFNDIM (4 * CDIM)          // 2048
#define QKVN  (3 * CDIM)           // 1536
#define NCHUNK 2
#define MHALF (MROWS / NCHUNK)     // 8192

// Scratch (allocation-free rule: __device__ globals)
__device__ __half g_h   [MROWS * CDIM];
__device__ __half g_qkv [MROWS * QKVN];
__device__ __half g_o   [MROWS * CDIM];
__device__ __half g_h2  [MROWS * CDIM];
__device__ __half g_ffn [MROWS * FFNDIM];
// fp16 weights, TRANSPOSED to [N][K] (K contiguous)
__device__ __half g_wqkv[QKVN * CDIM];
__device__ __half g_wp  [CDIM * CDIM];
__device__ __half g_w1  [FFNDIM * CDIM];
__device__ __half g_w2  [CDIM * FFNDIM];

// ---------------------------------------------------------------------------
// PTX helpers
// ---------------------------------------------------------------------------
__device__ __forceinline__ void mma_f16(float* c, const uint32_t* a, const uint32_t* b) {
    asm volatile(
        "mma.sync.aligned.m16n8k16.row.col.f32.f16.f16.f32 "
        "{%0,%1,%2,%3},{%4,%5,%6,%7},{%8,%9},{%0,%1,%2,%3};"
        : "+f"(c[0]), "+f"(c[1]), "+f"(c[2]), "+f"(c[3])
        : "r"(a[0]), "r"(a[1]), "r"(a[2]), "r"(a[3]), "r"(b[0]), "r"(b[1]));
}
__device__ __forceinline__ uint32_t smem_u32(const void* p) {
    return (uint32_t)__cvta_generic_to_shared(p);
}
__device__ __forceinline__ void cp16(uint32_t dst, const void* src) {
    asm volatile("cp.async.cg.shared.global [%0], [%1], 16;" :: "r"(dst), "l"(src));
}
__device__ __forceinline__ void cp_commit() { asm volatile("cp.async.commit_group;"); }
template<int N> __device__ __forceinline__ void cp_wait() {
    asm volatile("cp.async.wait_group %0;" :: "n"(N));
}
__device__ __forceinline__ void ldmx4(
    uint32_t& r0, uint32_t& r1, uint32_t& r2, uint32_t& r3, uint32_t addr)
{
    asm volatile("ldmatrix.sync.aligned.m8n8.x4.shared.b16 {%0,%1,%2,%3}, [%4];"
        : "=r"(r0), "=r"(r1), "=r"(r2), "=r"(r3) : "r"(addr));
}
__device__ __forceinline__ void ldmx4_trans(
    uint32_t& r0, uint32_t& r1, uint32_t& r2, uint32_t& r3, uint32_t addr)
{
    asm volatile("ldmatrix.sync.aligned.m8n8.x4.trans.shared.b16 {%0,%1,%2,%3}, [%4];"
        : "=r"(r0), "=r"(r1), "=r"(r2), "=r"(r3) : "r"(addr));
}

// ---------------------------------------------------------------------------
// Warp-per-row LayerNorm helper (C = 512)
// ---------------------------------------------------------------------------
__device__ __forceinline__ void ln_row_warp(
    const float* __restrict__ xr, const float* __restrict__ g,
    const float* __restrict__ b, __half* __restrict__ outr, int lane)
{
    float4 v[4];
    float s = 0.f, ss = 0.f;
    #pragma unroll
    for (int i = 0; i < 4; i++) {
        v[i] = *reinterpret_cast<const float4*>(&xr[lane * 4 + i * 128]);
        s  += v[i].x + v[i].y + v[i].z + v[i].w;
        ss += v[i].x*v[i].x + v[i].y*v[i].y + v[i].z*v[i].z + v[i].w*v[i].w;
    }
    #pragma unroll
    for (int off = 16; off > 0; off >>= 1) {
        s  += __shfl_xor_sync(0xffffffffu, s,  off);
        ss += __shfl_xor_sync(0xffffffffu, ss, off);
    }
    const float mu   = s * (1.0f / CDIM);
    const float var  = ss * (1.0f / CDIM) - mu * mu;
    const float rstd = rsqrtf(var + 1e-5f);
    #pragma unroll
    for (int i = 0; i < 4; i++) {
        const int col = lane * 4 + i * 128;
        float4 gg = *reinterpret_cast<const float4*>(&g[col]);
        float4 bb = *reinterpret_cast<const float4*>(&b[col]);
        __half2* op = reinterpret_cast<__half2*>(&outr[col]);
        op[0] = __floats2half2_rn((v[i].x - mu) * rstd * gg.x + bb.x,
                                  (v[i].y - mu) * rstd * gg.y + bb.y);
        op[1] = __floats2half2_rn((v[i].z - mu) * rstd * gg.z + bb.z,
                                  (v[i].w - mu) * rstd * gg.w + bb.w);
    }
}

// ---------------------------------------------------------------------------
// Tiled transpose helper: 32x32 tile of W[K][N] -> Wt[N][K] (fp16)
// ---------------------------------------------------------------------------
__device__ __forceinline__ void transpose_tile(
    const float* __restrict__ W, __half* __restrict__ Wt,
    int K, int N, int k0, int n0, int tid, float* sm /*32*33*/)
{
    const int tx = tid & 31, ty = tid >> 5;
    #pragma unroll
    for (int i = 0; i < 4; i++)
        sm[(ty + 8 * i) * 33 + tx] = W[(size_t)(k0 + ty + 8 * i) * N + n0 + tx];
    __syncthreads();
    #pragma unroll
    for (int i = 0; i < 4; i++)
        Wt[(size_t)(n0 + ty + 8 * i) * K + k0 + tx] =
            __float2half_rn(sm[tx * 33 + ty + 8 * i]);
}

// ---------------------------------------------------------------------------
// Fused prep: all 4 weight transposes + LN1, one launch, flat grid.
// ---------------------------------------------------------------------------
__global__ void __launch_bounds__(256) prep_fused(
    const float* __restrict__ wq, const float* __restrict__ wk,
    const float* __restrict__ wv, const float* __restrict__ w_proj,
    const float* __restrict__ w1, const float* __restrict__ w2,
    __half* __restrict__ wqkvT, __half* __restrict__ wpT,
    __half* __restrict__ w1T, __half* __restrict__ w2T,
    const float* __restrict__ x, const float* __restrict__ ln1_g,
    const float* __restrict__ ln1_b, __half* __restrict__ h)
{
    __shared__ float sm[32 * 33];
    const int bx  = blockIdx.x;
    const int tid = threadIdx.x;

    if (bx < 768) {
        const int k0 = (bx & 15) * 32, n0 = (bx >> 4) * 32;
        const int part = n0 >> 9, hh = (n0 >> 6) & 7, d0 = n0 & 32;
        const float* w = (part == 0) ? wq : (part == 1 ? wk : wv);
        const int tx = tid & 31, ty = tid >> 5;
        #pragma unroll
        for (int i = 0; i < 4; i++)
            sm[(ty + 8 * i) * 33 + tx] =
                w[((size_t)(hh * CDIM + k0 + ty + 8 * i)) * 64 + d0 + tx];
        __syncthreads();
        #pragma unroll
        for (int i = 0; i < 4; i++)
            wqkvT[(size_t)(n0 + ty + 8 * i) * CDIM + k0 + tx] =
                __float2half_rn(sm[tx * 33 + ty + 8 * i]);
    } else if (bx < 1024) {
        const int idx = bx - 768;
        transpose_tile(w_proj, wpT, CDIM, CDIM,
                       (idx & 15) * 32, (idx >> 4) * 32, tid, sm);
    } else if (bx < 2048) {
        const int idx = bx - 1024;
        transpose_tile(w1, w1T, CDIM, FFNDIM,
                       (idx & 15) * 32, (idx >> 4) * 32, tid, sm);
    } else if (bx < 3072) {
        const int idx = bx - 2048;
        transpose_tile(w2, w2T, FFNDIM, CDIM,
                       (idx & 63) * 32, (idx >> 6) * 32, tid, sm);
    } else {
        const int idx  = bx - 3072;
        const int warp = tid >> 5, lane = tid & 31;
        const int row  = idx * 8 + warp;
        ln_row_warp(x + (size_t)row * CDIM, ln1_g, ln1_b,
                    h + (size_t)row * CDIM, lane);
    }
}

__global__ void __launch_bounds__(256) ln_rows(
    const float* __restrict__ x, const float* __restrict__ g,
    const float* __restrict__ b, __half* __restrict__ out)
{
    const int warp = threadIdx.x >> 5, lane = threadIdx.x & 31;
    const int row  = blockIdx.x * 8 + warp;
    ln_row_warp(x + (size_t)row * CDIM, g, b, out + (size_t)row * CDIM, lane);
}

// ---------------------------------------------------------------------------
// fp16 tensor-core GEMM (R10 structure): BM=BN=128, BK=64, 128 threads,
// 4 warps (2x2), warp tile 64x64, 3-stage cp.async, ldmatrix.x4.
// ---------------------------------------------------------------------------
#define FBM 128
#define FBK 64
#define LDHG 72
#define TILE_H (FBM * LDHG)
#define NSTAGE 3
#define GSMEM_BYTES (NSTAGE * 2 * TILE_H * 2 + 1024 + 256)

template<typename OutT, bool BIAS, bool RELU, bool RES>
__global__ void __launch_bounds__(128, 2) gemm_f16(
    const __half* __restrict__ A, const __half* __restrict__ Bw,
    const float* __restrict__ bias, const float* __restrict__ res,
    OutT* __restrict__ C, int M, int N, int K)
{
    extern __shared__ char dsm[];
    __half* As = reinterpret_cast<__half*>(dsm);
    __half* Bs = As + NSTAGE * TILE_H;
    float* bias_s = reinterpret_cast<float*>(Bs + NSTAGE * TILE_H);

    const int tid  = threadIdx.x;
    const int w    = tid >> 5;
    const int lane = tid & 31;
    const int g    = lane >> 2;
    const int tg   = lane & 3;

    const int m0 = blockIdx.y * FBM;
    const int n0 = blockIdx.x * FBM;
    const int wm = (w & 1) * 64;
    const int wn = (w >> 1) * 64;

    if (BIAS) bias_s[tid] = bias[n0 + tid];

    float acc[4][8][4];
    #pragma unroll
    for (int mt = 0; mt < 4; mt++)
        #pragma unroll
        for (int nt = 0; nt < 8; nt++)
            #pragma unroll
            for (int i = 0; i < 4; i++) acc[mt][nt][i] = 0.0f;

    const uint32_t as_base = smem_u32(As);
    const uint32_t bs_base = smem_u32(Bs);

    auto load_tile = [&](int buf, int k0) {
        const uint32_t a_s = as_base + buf * TILE_H * 2;
        const uint32_t b_s = bs_base + buf * TILE_H * 2;
        #pragma unroll
        for (int j = 0; j < 8; j++) {
            int c = tid + 128 * j;
            int row = c >> 3, ch = c & 7;
            cp16(a_s + row * (LDHG * 2) + ch * 16,
                 A + (size_t)(m0 + row) * K + k0 + ch * 8);
            cp16(b_s + row * (LDHG * 2) + ch * 16,
                 Bw + (size_t)(n0 + row) * K + k0 + ch * 8);
        }
        cp_commit();
    };

    const int NIT = K / FBK;
    load_tile(0, 0);
    load_tile(1, FBK);
    load_tile(2, 2 * FBK);

    const int a_row = lane & 15;
    const int a_kof = (lane & 16) ? 8 : 0;
    const int b_row = (lane & 7) + ((lane & 16) ? 8 : 0);
    const int b_kof = (lane & 8) ? 8 : 0;

    for (int it = 0; it < NIT; it++) {
        const int buf = it % NSTAGE;
        if (it + 2 < NIT)      cp_wait<2>();
        else if (it + 1 < NIT) cp_wait<1>();
        else                   cp_wait<0>();
        __syncthreads();

        const __half* Ab = As + buf * TILE_H;
        const __half* Bb = Bs + buf * TILE_H;

        #pragma unroll
        for (int ks = 0; ks < 4; ks++) {
            const int kb = ks * 16;
            uint32_t af[4][4], bf[8][2];
            #pragma unroll
            for (int mt = 0; mt < 4; mt++) {
                uint32_t addr = smem_u32(
                    &Ab[(wm + mt * 16 + a_row) * LDHG + kb + a_kof]);
                ldmx4(af[mt][0], af[mt][1], af[mt][2], af[mt][3], addr);
            }
            #pragma unroll
            for (int p = 0; p < 4; p++) {
                uint32_t addr = smem_u32(
                    &Bb[(wn + p * 16 + b_row) * LDHG + kb + b_kof]);
                ldmx4(bf[2*p][0], bf[2*p][1], bf[2*p+1][0], bf[2*p+1][1], addr);
            }
            #pragma unroll
            for (int mt = 0; mt < 4; mt++)
                #pragma unroll
                for (int nt = 0; nt < 8; nt++)
                    mma_f16(acc[mt][nt], af[mt], bf[nt]);
        }
        __syncthreads();

        if (it + 3 < NIT) load_tile(buf, (it + 3) * FBK);
    }

    // Epilogue
    #pragma unroll
    for (int mt = 0; mt < 4; mt++) {
        #pragma unroll
        for (int nt = 0; nt < 8; nt++) {
            const int col = n0 + wn + nt * 8 + 2 * tg;
            float2 bb = make_float2(0.f, 0.f);
            if (BIAS) {
                bb.x = bias_s[wn + nt * 8 + 2 * tg];
                bb.y = bias_s[wn + nt * 8 + 2 * tg + 1];
            }
            #pragma unroll
            for (int half_i = 0; half_i < 2; half_i++) {
                const int row = m0 + wm + mt * 16 + g + half_i * 8;
                float2 v = make_float2(acc[mt][nt][half_i * 2 + 0],
                                       acc[mt][nt][half_i * 2 + 1]);
                if (BIAS) { v.x += bb.x; v.y += bb.y; }
                if (RES) {
                    float2 rr = *reinterpret_cast<const float2*>(
                        &res[(size_t)row * N + col]);
                    v.x += rr.x; v.y += rr.y;
                }
                if (RELU) { v.x = fmaxf(v.x, 0.f); v.y = fmaxf(v.y, 0.f); }
                if (sizeof(OutT) == 2) {
                    *reinterpret_cast<__half2*>(
                        reinterpret_cast<__half*>(C) + (size_t)row * N + col) =
                        __floats2half2_rn(v.x, v.y);
                } else {
                    *reinterpret_cast<float2*>(
                        reinterpret_cast<float*>(C) + (size_t)row * N + col) = v;
                }
            }
        }
    }
}

// ---------------------------------------------------------------------------
// fp16 tensor-core causal flash attention (R10 structure).
// ---------------------------------------------------------------------------
#define ALH 72
#define AQ_H (64 * ALH)
#define AK_H (64 * ALH)
#define AV_H (64 * ALH)
#define AP_H (16 * ALH)
#define ATTN_SMEM_BYTES ((AQ_H + 2*AK_H + 2*AV_H + 4*AP_H) * 2)

__global__ void __launch_bounds__(128) attn_f16(
    const __half* __restrict__ qkv, __half* __restrict__ o)
{
    extern __shared__ __half hsm[];
    __half* Qs = hsm;
    __half* Ks = Qs + AQ_H;
    __half* Vs = Ks + 2 * AK_H;
    __half* Ps = Vs + 2 * AV_H;

    const int qt  = (int)gridDim.x - 1 - (int)blockIdx.x;
    const int bh  = blockIdx.y;
    const int b   = bh >> 3;
    const int h   = bh & 7;
    const int tid = threadIdx.x;
    const int w   = tid >> 5;
    const int lane = tid & 31;
    const int g    = lane >> 2;
    const int tg   = lane & 3;
    const int q0  = qt * 64;

    const float scale = 0.04419417382415922f;   // 1/sqrt(512)

    const __half* qbase = qkv + ((size_t)(b * SEQ + q0)) * QKVN + h * DHEAD;
    const __half* kbase = qkv + ((size_t)b * SEQ) * QKVN + 512  + h * DHEAD;
    const __half* vbase = qkv + ((size_t)b * SEQ) * QKVN + 1024 + h * DHEAD;

    {
        const uint32_t qs = smem_u32(Qs);
        #pragma unroll
        for (int i = 0; i < 4; i++) {
            int c = tid + i * 128;
            int row = c >> 3, ch = c & 7;
            cp16(qs + row * (ALH * 2) + ch * 16,
                 qbase + (size_t)row * QKVN + ch * 8);
        }
        cp_commit();
    }

    auto issue_kv = [&](int buf, int j0) {
        const uint32_t ks = smem_u32(Ks + buf * AK_H);
        const uint32_t vs = smem_u32(Vs + buf * AV_H);
        #pragma unroll
        for (int i = 0; i < 4; i++) {
            int c = tid + i * 128;
            int row = c >> 3, ch = c & 7;
            cp16(ks + row * (ALH * 2) + ch * 16,
                 kbase + (size_t)(j0 + row) * QKVN + ch * 8);
            cp16(vs + row * (ALH * 2) + ch * 16,
                 vbase + (size_t)(j0 + row) * QKVN + ch * 8);
        }
        cp_commit();
    };

    issue_kv(0, 0);
    cp_wait<0>();
    __syncthreads();

    const int a_row = lane & 15;
    const int a_kof = (lane & 16) ? 8 : 0;
    const int b_row = (lane & 7) + ((lane & 16) ? 8 : 0);
    const int b_kof = (lane & 8) ? 8 : 0;

    uint32_t qf[4][4];
    #pragma unroll
    for (int kb = 0; kb < 4; kb++) {
        uint32_t addr = smem_u32(&Qs[(w * 16 + a_row) * ALH + kb * 16 + a_kof]);
        ldmx4(qf[kb][0], qf[kb][1], qf[kb][2], qf[kb][3], addr);
    }

    float oacc[8][4];
    #pragma unroll
    for (int nt = 0; nt < 8; nt++)
        #pragma unroll
        for (int i = 0; i < 4; i++) oacc[nt][i] = 0.0f;
    float m_lo = -INFINITY, m_hi = -INFINITY;
    float l_lo = 0.0f, l_hi = 0.0f;

    __half* Pw = Ps + w * AP_H;
    const int ntiles = qt + 1;

    for (int it = 0; it < ntiles; it++) {
        if (it + 1 < ntiles) {
            issue_kv((it + 1) & 1, (it + 1) * 64);
            cp_wait<1>();
        } else {
            cp_wait<0>();
        }
        __syncthreads();

        const __half* Kb = Ks + (it & 1) * AK_H;
        const __half* Vb = Vs + (it & 1) * AV_H;

        float sacc[8][4];
        #pragma unroll
        for (int nt = 0; nt < 8; nt++)
            #pragma unroll
            for (int i = 0; i < 4; i++) sacc[nt][i] = 0.0f;

        #pragma unroll
        for (int kb = 0; kb < 4; kb++) {
            uint32_t bf[8][2];
            #pragma unroll
            for (int p = 0; p < 4; p++) {
                uint32_t addr = smem_u32(
                    &Kb[(p * 16 + b_row) * ALH + kb * 16 + b_kof]);
                ldmx4(bf[2*p][0], bf[2*p][1], bf[2*p+1][0], bf[2*p+1][1], addr);
            }
            #pragma unroll
            for (int nt = 0; nt < 8; nt++)
                mma_f16(sacc[nt], qf[kb], bf[nt]);
        }

        const int j0 = it * 64;
        const bool diag = (it == ntiles - 1) && (j0 == q0);
        const int qr_lo = q0 + w * 16 + g;
        const int qr_hi = qr_lo + 8;
        #pragma unroll
        for (int nt = 0; nt < 8; nt++) {
            const int c0 = j0 + nt * 8 + 2 * tg;
            sacc[nt][0] = (diag && c0     > qr_lo) ? -INFINITY : sacc[nt][0] * scale;
            sacc[nt][1] = (diag && c0 + 1 > qr_lo) ? -INFINITY : sacc[nt][1] * scale;
            sacc[nt][2] = (diag && c0     > qr_hi) ? -INFINITY : sacc[nt][2] * scale;
            sacc[nt][3] = (diag && c0 + 1 > qr_hi) ? -INFINITY : sacc[nt][3] * scale;
        }

        float mx_lo = -INFINITY, mx_hi = -INFINITY;
        #pragma unroll
        for (int nt = 0; nt < 8; nt++) {
            mx_lo = fmaxf(mx_lo, fmaxf(sacc[nt][0], sacc[nt][1]));
            mx_hi = fmaxf(mx_hi, fmaxf(sacc[nt][2], sacc[nt][3]));
        }
        mx_lo = fmaxf(mx_lo, __shfl_xor_sync(0xffffffffu, mx_lo, 1));
        mx_lo = fmaxf(mx_lo, __shfl_xor_sync(0xffffffffu, mx_lo, 2));
        mx_hi = fmaxf(mx_hi, __shfl_xor_sync(0xffffffffu, mx_hi, 1));
        mx_hi = fmaxf(mx_hi, __shfl_xor_sync(0xffffffffu, mx_hi, 2));

        const float mn_lo = fmaxf(m_lo, mx_lo);
        const float mn_hi = fmaxf(m_hi, mx_hi);
        const float c_lo = __expf(m_lo - mn_lo);
        const float c_hi = __expf(m_hi - mn_hi);
        m_lo = mn_lo; m_hi = mn_hi;

        float ts_lo = 0.0f, ts_hi = 0.0f;
        #pragma unroll
        for (int nt = 0; nt < 8; nt++) {
            float p0 = __expf(sacc[nt][0] - m_lo);
            float p1 = __expf(sacc[nt][1] - m_lo);
            float p2 = __expf(sacc[nt][2] - m_hi);
            float p3 = __expf(sacc[nt][3] - m_hi);
            ts_lo += p0 + p1;
            ts_hi += p2 + p3;
            *reinterpret_cast<__half2*>(&Pw[(g    ) * ALH + nt * 8 + 2 * tg]) =
                __floats2half2_rn(p0, p1);
            *reinterpret_cast<__half2*>(&Pw[(g + 8) * ALH + nt * 8 + 2 * tg]) =
                __floats2half2_rn(p2, p3);
        }
        ts_lo += __shfl_xor_sync(0xffffffffu, ts_lo, 1);
        ts_lo += __shfl_xor_sync(0xffffffffu, ts_lo, 2);
        ts_hi += __shfl_xor_sync(0xffffffffu, ts_hi, 1);
        ts_hi += __shfl_xor_sync(0xffffffffu, ts_hi, 2);
        l_lo = l_lo * c_lo + ts_lo;
        l_hi = l_hi * c_hi + ts_hi;

        #pragma unroll
        for (int nt = 0; nt < 8; nt++) {
            oacc[nt][0] *= c_lo; oacc[nt][1] *= c_lo;
            oacc[nt][2] *= c_hi; oacc[nt][3] *= c_hi;
        }
        __syncwarp();

        #pragma unroll
        for (int kt = 0; kt < 4; kt++) {
            uint32_t af[4];
            {
                uint32_t addr = smem_u32(&Pw[a_row * ALH + kt * 16 + a_kof]);
                ldmx4(af[0], af[1], af[2], af[3], addr);
            }
            #pragma unroll
            for (int nt = 0; nt < 8; nt += 2) {
                const int vrow = kt * 16 + (lane & 15);
                const int vcol = (nt + (lane >> 4)) * 8;
                uint32_t addr = smem_u32(&Vb[vrow * ALH + vcol]);
                uint32_t b0, b1, b2, b3;
                ldmx4_trans(b0, b1, b2, b3, addr);
                uint32_t bf0[2] = {b0, b1};
                uint32_t bf1[2] = {b2, b3};
                mma_f16(oacc[nt],     af, bf0);
                mma_f16(oacc[nt + 1], af, bf1);
            }
        }
        __syncthreads();
    }

    const float inv_lo = 1.0f / l_lo;
    const float inv_hi = 1.0f / l_hi;
    const int qr = q0 + w * 16 + g;
    __half* orow_lo = o + ((size_t)(b * SEQ + qr    )) * CDIM + h * DHEAD;
    __half* orow_hi = o + ((size_t)(b * SEQ + qr + 8)) * CDIM + h * DHEAD;
    #pragma unroll
    for (int nt = 0; nt < 8; nt++) {
        const int col = nt * 8 + 2 * tg;
        *reinterpret_cast<__half2*>(&orow_lo[col]) =
            __floats2half2_rn(oacc[nt][0] * inv_lo, oacc[nt][1] * inv_lo);
        *reinterpret_cast<__half2*>(&orow_hi[col]) =
            __floats2half2_rn(oacc[nt][2] * inv_hi, oacc[nt][3] * inv_hi);
    }
}

// ---------------------------------------------------------------------------
// Launch. Inputs: 0:x 1:wq 2:wk 3:wv 4:w_proj 5:b_proj 6:w1 7:b1 8:w2 9:b2
//                 10:ln1_g 11:ln1_b 12:ln2_g 13:ln2_b
// Two-stream row-chunked pipeline: after prep (LN1 + weight transposes),
// each half of M runs its full chain on its own non-blocking stream.
// ---------------------------------------------------------------------------
extern "C" void kernel_launch(void* const* d_in, const int* in_sizes, int n_in,
                              void* d_out, int out_size)
{
    const float* x      = (const float*)d_in[0];
    const float* wq     = (const float*)d_in[1];
    const float* wk     = (const float*)d_in[2];
    const float* wv     = (const float*)d_in[3];
    const float* w_proj = (const float*)d_in[4];
    const float* b_proj = (const float*)d_in[5];
    const float* w1     = (const float*)d_in[6];
    const float* b1     = (const float*)d_in[7];
    const float* w2     = (const float*)d_in[8];
    const float* b2     = (const float*)d_in[9];
    const float* ln1_g  = (const float*)d_in[10];
    const float* ln1_b  = (const float*)d_in[11];
    const float* ln2_g  = (const float*)d_in[12];
    const float* ln2_b  = (const float*)d_in[13];
    float* out = (float*)d_out;

    __half *h, *qkv, *ob, *h2, *ffn, *w_qkvT, *w_pT, *w_1T, *w_2T;
    cudaGetSymbolAddress((void**)&h,      g_h);
    cudaGetSymbolAddress((void**)&qkv,    g_qkv);
    cudaGetSymbolAddress((void**)&ob,     g_o);
    cudaGetSymbolAddress((void**)&h2,     g_h2);
    cudaGetSymbolAddress((void**)&ffn,    g_ffn);
    cudaGetSymbolAddress((void**)&w_qkvT, g_wqkv);
    cudaGetSymbolAddress((void**)&w_pT,   g_wp);
    cudaGetSymbolAddress((void**)&w_1T,   g_w1);
    cudaGetSymbolAddress((void**)&w_2T,   g_w2);

    static bool init_done = false;
    static cudaStream_t st[NCHUNK];
    static cudaEvent_t ev_fork;
    static cudaEvent_t ev_join[NCHUNK];
    if (!init_done) {
        cudaFuncSetAttribute(attn_f16,
            cudaFuncAttributeMaxDynamicSharedMemorySize, ATTN_SMEM_BYTES);
        cudaFuncSetAttribute(gemm_f16<__half, false, false, false>,
            cudaFuncAttributeMaxDynamicSharedMemorySize, GSMEM_BYTES);
        cudaFuncSetAttribute(gemm_f16<float, true, false, true>,
            cudaFuncAttributeMaxDynamicSharedMemorySize, GSMEM_BYTES);
        cudaFuncSetAttribute(gemm_f16<__half, true, true, false>,
            cudaFuncAttributeMaxDynamicSharedMemorySize, GSMEM_BYTES);
        for (int i = 0; i < NCHUNK; i++) {
            cudaStreamCreateWithFlags(&st[i], cudaStreamNonBlocking);
            cudaEventCreateWithFlags(&ev_join[i], cudaEventDisableTiming);
        }
        cudaEventCreateWithFlags(&ev_fork, cudaEventDisableTiming);
        init_done = true;
    }

    // Prep on the launch (capturing) stream: weight transposes + LN1
    prep_fused<<<5120, 256>>>(wq, wk, wv, w_proj, w1, w2,
                              w_qkvT, w_pT, w_1T, w_2T,
                              x, ln1_g, ln1_b, h);

    // Fork
    cudaEventRecord(ev_fork, 0);

    for (int c = 0; c < NCHUNK; c++) {
        cudaStreamWaitEvent(st[c], ev_fork, 0);
        const size_t ro  = (size_t)c * MHALF;              // row offset

        // qkv projection for this half (fp16 out)
        gemm_f16<__half, false, false, false>
            <<<dim3(QKVN / FBM, MHALF / FBM), 128, GSMEM_BYTES, st[c]>>>(
            h + ro * CDIM, w_qkvT, nullptr, nullptr,
            qkv + ro * QKVN, MHALF, QKVN, CDIM);

        // attention for this half's batches (16 batches x 8 heads)
        attn_f16<<<dim3(SEQ / 64, (BATCH / NCHUNK) * NHEAD), 128,
                   ATTN_SMEM_BYTES, st[c]>>>(
            qkv + ro * QKVN, ob + ro * CDIM);

        // proj + residual -> out (fp32)
        gemm_f16<float, true, false, true>
            <<<dim3(CDIM / FBM, MHALF / FBM), 128, GSMEM_BYTES, st[c]>>>(
            ob + ro * CDIM, w_pT, b_proj, x + ro * CDIM,
            out + ro * CDIM, MHALF, CDIM, CDIM);

        // ln2 (fp16 out)
        ln_rows<<<MHALF / 8, 256, 0, st[c]>>>(
            out + ro * CDIM, ln2_g, ln2_b, h2 + ro * CDIM);

        // ffn1 = relu(h2 @ w1 + b1) (fp16 out)
        gemm_f16<__half, true, true, false>
            <<<dim3(FFNDIM / FBM, MHALF / FBM), 128, GSMEM_BYTES, st[c]>>>(
            h2 + ro * CDIM, w_1T, b1, nullptr,
            ffn + ro * FFNDIM, MHALF, FFNDIM, CDIM);

        // out += ffn1 @ w2 + b2 (fp32)
        gemm_f16<float, true, false, true>
            <<<dim3(CDIM / FBM, MHALF / FBM), 128, GSMEM_BYTES, st[c]>>>(
            ffn + ro * FFNDIM, w_2T, b2, out + ro * CDIM,
            out + ro * CDIM, MHALF, CDIM, FFNDIM);

        cudaEventRecord(ev_join[c], st[c]);
    }

    // Join back to the launch stream
    for (int c = 0; c < NCHUNK; c++)
        cudaStreamWaitEvent(0, ev_join[c], 0);
}